// round 2
// baseline (speedup 1.0000x reference)
#include <cuda_runtime.h>
#include <math.h>

// Problem constants
#define D_MODEL 1024
#define N_HEADS 16
#define D_HEAD  64
#define BATCH   2
#define SEQ     2048
#define M_TOT   (BATCH * SEQ)       // 4096
#define QKV_N   (3 * D_MODEL)       // 3072

// ---------------------------------------------------------------------------
// Scratch (no allocs allowed -> __device__ globals)
// ---------------------------------------------------------------------------
__device__ float g_qkv[(size_t)M_TOT * QKV_N];                    // 48 MB
__device__ float g_q[(size_t)BATCH * N_HEADS * SEQ * D_HEAD];     // 16 MB
__device__ float g_k[(size_t)BATCH * N_HEADS * SEQ * D_HEAD];     // 16 MB
__device__ float g_v[(size_t)BATCH * N_HEADS * SEQ * D_HEAD];     // 16 MB
__device__ float g_ctx[(size_t)M_TOT * D_MODEL];                  // 16 MB

// ---------------------------------------------------------------------------
// Tiled fp32 SGEMM:  C[m][n] = sum_k A[m][k] * W[n][k] + bias[n]
// BM=128, BN=128, BK=8, 256 threads, 8x8 per-thread micro-tile.
// Requires M%128==0, N%128==0, K%8==0 (true for all our shapes).
// ---------------------------------------------------------------------------
__global__ __launch_bounds__(256) void sgemm_bias_kernel(
    const float* __restrict__ A, const float* __restrict__ W,
    const float* __restrict__ bias, float* __restrict__ C,
    int M, int N, int K)
{
    __shared__ float As[8][128];
    __shared__ float Bs[8][128];

    const int tid = threadIdx.x;
    const int m0 = blockIdx.y * 128;
    const int n0 = blockIdx.x * 128;
    const int ty = tid >> 4;         // 0..15
    const int tx = tid & 15;         // 0..15

    // Load mapping: each thread loads one float4 of A and one of B per k-tile.
    const int lrow = tid >> 1;       // 0..127
    const int lcol = (tid & 1) * 4;  // 0 or 4

    float acc[8][8];
#pragma unroll
    for (int i = 0; i < 8; i++)
#pragma unroll
        for (int j = 0; j < 8; j++) acc[i][j] = 0.0f;

    const float* aPtr = A + (size_t)(m0 + lrow) * K + lcol;
    const float* bPtr = W + (size_t)(n0 + lrow) * K + lcol;

    for (int k0 = 0; k0 < K; k0 += 8) {
        float4 av = *(const float4*)(aPtr + k0);
        float4 bv = *(const float4*)(bPtr + k0);
        As[lcol + 0][lrow] = av.x;
        As[lcol + 1][lrow] = av.y;
        As[lcol + 2][lrow] = av.z;
        As[lcol + 3][lrow] = av.w;
        Bs[lcol + 0][lrow] = bv.x;
        Bs[lcol + 1][lrow] = bv.y;
        Bs[lcol + 2][lrow] = bv.z;
        Bs[lcol + 3][lrow] = bv.w;
        __syncthreads();

#pragma unroll
        for (int kk = 0; kk < 8; kk++) {
            float aF[8], bF[8];
            *(float4*)&aF[0] = *(const float4*)&As[kk][ty * 8];
            *(float4*)&aF[4] = *(const float4*)&As[kk][ty * 8 + 4];
            *(float4*)&bF[0] = *(const float4*)&Bs[kk][tx * 8];
            *(float4*)&bF[4] = *(const float4*)&Bs[kk][tx * 8 + 4];
#pragma unroll
            for (int i = 0; i < 8; i++)
#pragma unroll
                for (int j = 0; j < 8; j++)
                    acc[i][j] = fmaf(aF[i], bF[j], acc[i][j]);
        }
        __syncthreads();
    }

#pragma unroll
    for (int i = 0; i < 8; i++) {
        const int m = m0 + ty * 8 + i;
        float* crow = C + (size_t)m * N + n0 + tx * 8;
        const float* brow = bias + n0 + tx * 8;
#pragma unroll
        for (int j = 0; j < 8; j += 4) {
            float4 o;
            o.x = acc[i][j + 0] + brow[j + 0];
            o.y = acc[i][j + 1] + brow[j + 1];
            o.z = acc[i][j + 2] + brow[j + 2];
            o.w = acc[i][j + 3] + brow[j + 3];
            *(float4*)(crow + j) = o;
        }
    }
}

// ---------------------------------------------------------------------------
// RoPE + split: g_qkv [B*S, 3*D] -> g_q/g_k/g_v in [B, H, S, Dh] layout.
// rotate_half(x)[d] = -x[d+32] (d<32), x[d-32] (d>=32); pair index = d^32.
// ---------------------------------------------------------------------------
__global__ void rope_split_kernel(const float* __restrict__ qkv,
                                  float* __restrict__ Q,
                                  float* __restrict__ Kp,
                                  float* __restrict__ Vp)
{
    const int idx = blockIdx.x * blockDim.x + threadIdx.x;
    const int total = BATCH * SEQ * N_HEADS * D_HEAD;
    if (idx >= total) return;

    const int d = idx & 63;
    const int h = (idx >> 6) & (N_HEADS - 1);
    const int s = (idx >> 10) & (SEQ - 1);
    const int b = idx >> 21;

    const float* row = qkv + (size_t)(b * SEQ + s) * QKV_N;
    const int hd = h * 64 + d;
    const int hp = h * 64 + (d ^ 32);

    const float qv = row[hd];
    const float kv = row[D_MODEL + hd];
    const float vv = row[2 * D_MODEL + hd];
    const float qp = row[hp];
    const float kp = row[D_MODEL + hp];

    const int j = d & 31;
    const float inv = powf(10000.0f, -(float)j / 32.0f);
    const float ang = (float)s * inv;
    const float c = cosf(ang);
    const float sn = sinf(ang);

    const float qr = (d < 32) ? -qp : qp;
    const float kr = (d < 32) ? -kp : kp;

    const size_t o = ((size_t)(b * N_HEADS + h) * SEQ + s) * D_HEAD + d;
    Q[o] = qv * c + qr * sn;
    Kp[o] = kv * c + kr * sn;
    Vp[o] = vv;
}

// ---------------------------------------------------------------------------
// Causal flash attention (fp32). 1 query per thread, 128 queries/block,
// 64-key K/V tiles in shared, online softmax, tile-level causal skip.
// Output -> g_ctx in [B, S, H*Dh] layout (ready for the proj GEMM).
// ---------------------------------------------------------------------------
__global__ __launch_bounds__(128) void flash_attn_kernel(
    const float* __restrict__ Q, const float* __restrict__ K,
    const float* __restrict__ V, float* __restrict__ ctx)
{
    const int qt = blockIdx.x;           // query tile (128 rows)
    const int h  = blockIdx.y;
    const int b  = blockIdx.z;
    const int tid = threadIdx.x;
    const int qi = qt * 128 + tid;       // global query index

    __shared__ float Ks[64][64];
    __shared__ float Vs[64][64];

    const size_t headBase = (size_t)(b * N_HEADS + h) * SEQ * D_HEAD;
    const float* qrow = Q + headBase + (size_t)qi * D_HEAD;

    float qreg[64];
#pragma unroll
    for (int i = 0; i < 16; i++)
        *(float4*)&qreg[i * 4] = *(const float4*)&qrow[i * 4];

    float acc[64];
#pragma unroll
    for (int d = 0; d < 64; d++) acc[d] = 0.0f;
    float mval = -1e30f;
    float lsum = 0.0f;

    const float scale = 0.125f;          // 1/sqrt(64)
    const float* Kb = K + headBase;
    const float* Vb = V + headBase;

    const int ntiles = qt * 2 + 2;       // tiles with t0 <= max query in block
    for (int nt = 0; nt < ntiles; nt++) {
        const int t0 = nt * 64;
        // cooperative tile load: 64 rows x 16 float4
        for (int u = tid; u < 64 * 16; u += 128) {
            const int r = u >> 4;
            const int cc = (u & 15) * 4;
            *(float4*)&Ks[r][cc] = *(const float4*)&Kb[(size_t)(t0 + r) * 64 + cc];
            *(float4*)&Vs[r][cc] = *(const float4*)&Vb[(size_t)(t0 + r) * 64 + cc];
        }
        __syncthreads();

        const int jmax = min(64, qi - t0 + 1);   // keys with index <= qi
        for (int j = 0; j < jmax; j++) {
            float s0 = 0.f, s1 = 0.f, s2 = 0.f, s3 = 0.f;
#pragma unroll
            for (int d = 0; d < 64; d += 4) {
                s0 = fmaf(qreg[d + 0], Ks[j][d + 0], s0);
                s1 = fmaf(qreg[d + 1], Ks[j][d + 1], s1);
                s2 = fmaf(qreg[d + 2], Ks[j][d + 2], s2);
                s3 = fmaf(qreg[d + 3], Ks[j][d + 3], s3);
            }
            const float sv = ((s0 + s1) + (s2 + s3)) * scale;
            if (sv > mval) {
                const float f = expf(mval - sv);   // 0 on first key (mval=-1e30)
#pragma unroll
                for (int d = 0; d < 64; d++) acc[d] *= f;
                lsum *= f;
                mval = sv;
            }
            const float p = expf(sv - mval);
            lsum += p;
#pragma unroll
            for (int d = 0; d < 64; d++)
                acc[d] = fmaf(p, Vs[j][d], acc[d]);
        }
        __syncthreads();
    }

    const float invl = 1.0f / lsum;
    float* orow = ctx + (size_t)(b * SEQ + qi) * D_MODEL + h * 64;
#pragma unroll
    for (int d = 0; d < 64; d += 4) {
        float4 o;
        o.x = acc[d + 0] * invl;
        o.y = acc[d + 1] * invl;
        o.z = acc[d + 2] * invl;
        o.w = acc[d + 3] * invl;
        *(float4*)(orow + d) = o;
    }
}

// ---------------------------------------------------------------------------
// Launch
// ---------------------------------------------------------------------------
extern "C" void kernel_launch(void* const* d_in, const int* in_sizes, int n_in,
                              void* d_out, int out_size)
{
    const float* x      = (const float*)d_in[0];
    const float* qkv_w  = (const float*)d_in[1];
    const float* qkv_b  = (const float*)d_in[2];
    const float* proj_w = (const float*)d_in[3];
    const float* proj_b = (const float*)d_in[4];
    float* out = (float*)d_out;

    float *p_qkv, *p_q, *p_k, *p_v, *p_ctx;
    cudaGetSymbolAddress((void**)&p_qkv, g_qkv);
    cudaGetSymbolAddress((void**)&p_q,   g_q);
    cudaGetSymbolAddress((void**)&p_k,   g_k);
    cudaGetSymbolAddress((void**)&p_v,   g_v);
    cudaGetSymbolAddress((void**)&p_ctx, g_ctx);

    // 1) QKV projection: [4096,1024] x [3072,1024]^T -> [4096,3072]
    sgemm_bias_kernel<<<dim3(QKV_N / 128, M_TOT / 128), 256>>>(
        x, qkv_w, qkv_b, p_qkv, M_TOT, QKV_N, D_MODEL);

    // 2) RoPE + split into [B,H,S,Dh]
    {
        const int total = BATCH * SEQ * N_HEADS * D_HEAD;
        rope_split_kernel<<<(total + 255) / 256, 256>>>(p_qkv, p_q, p_k, p_v);
    }

    // 3) Causal flash attention -> ctx [B,S,D]
    flash_attn_kernel<<<dim3(SEQ / 128, N_HEADS, BATCH), 128>>>(p_q, p_k, p_v, p_ctx);

    // 4) Output projection: [4096,1024] x [1024,1024]^T -> [4096,1024]
    sgemm_bias_kernel<<<dim3(D_MODEL / 128, M_TOT / 128), 256>>>(
        p_ctx, proj_w, proj_b, out, M_TOT, D_MODEL, D_MODEL);
}

// round 3
// speedup vs baseline: 1.4801x; 1.4801x over previous
#include <cuda_runtime.h>
#include <math.h>
#include <stdint.h>

// Problem constants
#define D_MODEL 1024
#define N_HEADS 16
#define D_HEAD  64
#define BATCH   2
#define SEQ     2048
#define M_TOT   (BATCH * SEQ)       // 4096
#define QKV_N   (3 * D_MODEL)       // 3072

// ---------------------------------------------------------------------------
// Scratch (no allocs allowed -> __device__ globals)
// ---------------------------------------------------------------------------
__device__ float g_qkv[(size_t)M_TOT * QKV_N];                    // 48 MB
__device__ float g_q[(size_t)BATCH * N_HEADS * SEQ * D_HEAD];     // 16 MB
__device__ float g_k[(size_t)BATCH * N_HEADS * SEQ * D_HEAD];     // 16 MB
__device__ float g_v[(size_t)BATCH * N_HEADS * SEQ * D_HEAD];     // 16 MB
__device__ float g_ctx[(size_t)M_TOT * D_MODEL];                  // 16 MB

// ---------------------------------------------------------------------------
// tf32 tensor-core GEMM: C[m][n] = sum_k A[m][k]*W[n][k] + bias[n]
// BM=BN=128, BK=32, 256 threads (8 warps in 2x4), warp tile 64x32,
// mma.sync.m16n8k8.tf32, cp.async double-buffered dynamic smem.
// Requires M%128==0, N%128==0, K%32==0.
// ---------------------------------------------------------------------------
#define GBM 128
#define GBN 128
#define GBK 32
#define GPAD 36                       // 32 + 4 pad (conflict-free frag loads)
#define ABUF (GBM * GPAD)             // floats per A stage
#define BBUF (GBN * GPAD)
#define GEMM_SMEM_BYTES ((2 * ABUF + 2 * BBUF) * 4)   // 73728

__device__ __forceinline__ uint32_t cvt_tf32(float f) {
    uint32_t u;
    asm volatile("cvt.rna.tf32.f32 %0, %1;" : "=r"(u) : "f"(f));
    return u;
}

__device__ __forceinline__ void mma_tf32(float c[4], const uint32_t a[4],
                                         const uint32_t b[2]) {
    asm volatile(
        "mma.sync.aligned.m16n8k8.row.col.f32.tf32.tf32.f32 "
        "{%0,%1,%2,%3}, {%4,%5,%6,%7}, {%8,%9}, {%0,%1,%2,%3};"
        : "+f"(c[0]), "+f"(c[1]), "+f"(c[2]), "+f"(c[3])
        : "r"(a[0]), "r"(a[1]), "r"(a[2]), "r"(a[3]), "r"(b[0]), "r"(b[1]));
}

#define CP_ASYNC16(dst, src) \
    asm volatile("cp.async.cg.shared.global [%0], [%1], 16;" :: "r"(dst), "l"(src))
#define CP_COMMIT() asm volatile("cp.async.commit_group;")
#define CP_WAIT0()  asm volatile("cp.async.wait_group 0;" ::: "memory")

__global__ __launch_bounds__(256) void gemm_tf32_kernel(
    const float* __restrict__ A, const float* __restrict__ W,
    const float* __restrict__ bias, float* __restrict__ C,
    int M, int N, int K)
{
    extern __shared__ float smem[];
    float* As = smem;                    // [2][128][36]
    float* Bs = smem + 2 * ABUF;         // [2][128][36]

    const int tid  = threadIdx.x;
    const int warp = tid >> 5;
    const int lane = tid & 31;
    const int warpM = warp >> 2;         // 0..1
    const int warpN = warp & 3;          // 0..3
    const int g   = lane >> 2;           // 0..7
    const int tig = lane & 3;            // 0..3

    const int m0 = blockIdx.y * GBM;
    const int n0 = blockIdx.x * GBN;

    float acc[4][4][4];
#pragma unroll
    for (int i = 0; i < 4; i++)
#pragma unroll
        for (int j = 0; j < 4; j++)
#pragma unroll
            for (int r = 0; r < 4; r++) acc[i][j][r] = 0.0f;

    uint32_t sA, sB;
    asm("{ .reg .u64 t; cvta.to.shared.u64 t, %1; cvt.u32.u64 %0, t; }"
        : "=r"(sA) : "l"(As));
    asm("{ .reg .u64 t; cvta.to.shared.u64 t, %1; cvt.u32.u64 %0, t; }"
        : "=r"(sB) : "l"(Bs));

    const int nkb = K / GBK;

    // Each thread copies 4 float4 for A and 4 for B per stage.
    // idx = tid + i*256 -> row = idx>>3 (0..127), c4 = idx&7 (f4 within 32 k).
    auto issue_stage = [&](int kb, int buf) {
#pragma unroll
        for (int i = 0; i < 4; i++) {
            const int idx = tid + i * 256;
            const int row = idx >> 3;
            const int c4  = idx & 7;
            const float* gsrcA = A + (size_t)(m0 + row) * K + kb * GBK + c4 * 4;
            const float* gsrcB = W + (size_t)(n0 + row) * K + kb * GBK + c4 * 4;
            const uint32_t off = (uint32_t)((row * GPAD + c4 * 4) * 4);
            CP_ASYNC16(sA + (uint32_t)(buf * ABUF * 4) + off, gsrcA);
            CP_ASYNC16(sB + (uint32_t)(buf * BBUF * 4) + off, gsrcB);
        }
    };

    issue_stage(0, 0);
    CP_COMMIT();

    for (int kb = 0; kb < nkb; kb++) {
        CP_WAIT0();
        __syncthreads();
        if (kb + 1 < nkb) {
            issue_stage(kb + 1, (kb + 1) & 1);
            CP_COMMIT();
        }

        const float* Ab = As + (kb & 1) * ABUF;
        const float* Bb = Bs + (kb & 1) * BBUF;

#pragma unroll
        for (int ks = 0; ks < 4; ks++) {
            const int k8 = ks * 8;
            uint32_t aF[4][4];
#pragma unroll
            for (int mt = 0; mt < 4; mt++) {
                const int mr = warpM * 64 + mt * 16;
                aF[mt][0] = cvt_tf32(Ab[(mr + g)     * GPAD + k8 + tig]);
                aF[mt][1] = cvt_tf32(Ab[(mr + g + 8) * GPAD + k8 + tig]);
                aF[mt][2] = cvt_tf32(Ab[(mr + g)     * GPAD + k8 + tig + 4]);
                aF[mt][3] = cvt_tf32(Ab[(mr + g + 8) * GPAD + k8 + tig + 4]);
            }
            uint32_t bF[4][2];
#pragma unroll
            for (int nt = 0; nt < 4; nt++) {
                const int nr = warpN * 32 + nt * 8 + g;
                bF[nt][0] = cvt_tf32(Bb[nr * GPAD + k8 + tig]);
                bF[nt][1] = cvt_tf32(Bb[nr * GPAD + k8 + tig + 4]);
            }
#pragma unroll
            for (int mt = 0; mt < 4; mt++)
#pragma unroll
                for (int nt = 0; nt < 4; nt++)
                    mma_tf32(acc[mt][nt], aF[mt], bF[nt]);
        }
        __syncthreads();
    }

    // Epilogue: acc tile (mt,nt): rows g,g+8 ; cols 2tig,2tig+1
#pragma unroll
    for (int mt = 0; mt < 4; mt++) {
        const int r0 = m0 + warpM * 64 + mt * 16 + g;
#pragma unroll
        for (int nt = 0; nt < 4; nt++) {
            const int col = n0 + warpN * 32 + nt * 8 + 2 * tig;
            const float2 b2 = *(const float2*)&bias[col];
            float2 o0, o1;
            o0.x = acc[mt][nt][0] + b2.x;
            o0.y = acc[mt][nt][1] + b2.y;
            o1.x = acc[mt][nt][2] + b2.x;
            o1.y = acc[mt][nt][3] + b2.y;
            *(float2*)&C[(size_t)r0 * N + col]       = o0;
            *(float2*)&C[(size_t)(r0 + 8) * N + col] = o1;
        }
    }
}

// ---------------------------------------------------------------------------
// RoPE + split: g_qkv [B*S, 3*D] -> g_q/g_k/g_v in [B, H, S, Dh] layout.
// ---------------------------------------------------------------------------
__global__ void rope_split_kernel(const float* __restrict__ qkv,
                                  float* __restrict__ Q,
                                  float* __restrict__ Kp,
                                  float* __restrict__ Vp)
{
    const int idx = blockIdx.x * blockDim.x + threadIdx.x;
    const int total = BATCH * SEQ * N_HEADS * D_HEAD;
    if (idx >= total) return;

    const int d = idx & 63;
    const int h = (idx >> 6) & (N_HEADS - 1);
    const int s = (idx >> 10) & (SEQ - 1);
    const int b = idx >> 21;

    const float* row = qkv + (size_t)(b * SEQ + s) * QKV_N;
    const int hd = h * 64 + d;
    const int hp = h * 64 + (d ^ 32);

    const float qv = row[hd];
    const float kv = row[D_MODEL + hd];
    const float vv = row[2 * D_MODEL + hd];
    const float qp = row[hp];
    const float kp = row[D_MODEL + hp];

    const int j = d & 31;
    const float inv = powf(10000.0f, -(float)j / 32.0f);
    const float ang = (float)s * inv;
    const float c = cosf(ang);
    const float sn = sinf(ang);

    const float qr = (d < 32) ? -qp : qp;
    const float kr = (d < 32) ? -kp : kp;

    const size_t o = ((size_t)(b * N_HEADS + h) * SEQ + s) * D_HEAD + d;
    Q[o] = qv * c + qr * sn;
    Kp[o] = kv * c + kr * sn;
    Vp[o] = vv;
}

// ---------------------------------------------------------------------------
// Causal flash attention (fp32). 1 query per thread, 128 queries/block,
// 64-key K/V tiles in shared, online softmax, tile-level causal skip.
// ---------------------------------------------------------------------------
__global__ __launch_bounds__(128) void flash_attn_kernel(
    const float* __restrict__ Q, const float* __restrict__ K,
    const float* __restrict__ V, float* __restrict__ ctx)
{
    const int qt = blockIdx.x;
    const int h  = blockIdx.y;
    const int b  = blockIdx.z;
    const int tid = threadIdx.x;
    const int qi = qt * 128 + tid;

    __shared__ float Ks[64][64];
    __shared__ float Vs[64][64];

    const size_t headBase = (size_t)(b * N_HEADS + h) * SEQ * D_HEAD;
    const float* qrow = Q + headBase + (size_t)qi * D_HEAD;

    float qreg[64];
#pragma unroll
    for (int i = 0; i < 16; i++)
        *(float4*)&qreg[i * 4] = *(const float4*)&qrow[i * 4];

    float acc[64];
#pragma unroll
    for (int d = 0; d < 64; d++) acc[d] = 0.0f;
    float mval = -1e30f;
    float lsum = 0.0f;

    const float scale = 0.125f;
    const float* Kb = K + headBase;
    const float* Vb = V + headBase;

    const int ntiles = qt * 2 + 2;
    for (int nt = 0; nt < ntiles; nt++) {
        const int t0 = nt * 64;
        for (int u = tid; u < 64 * 16; u += 128) {
            const int r = u >> 4;
            const int cc = (u & 15) * 4;
            *(float4*)&Ks[r][cc] = *(const float4*)&Kb[(size_t)(t0 + r) * 64 + cc];
            *(float4*)&Vs[r][cc] = *(const float4*)&Vb[(size_t)(t0 + r) * 64 + cc];
        }
        __syncthreads();

        const int jmax = min(64, qi - t0 + 1);
        for (int j = 0; j < jmax; j++) {
            float s0 = 0.f, s1 = 0.f, s2 = 0.f, s3 = 0.f;
#pragma unroll
            for (int d = 0; d < 64; d += 4) {
                s0 = fmaf(qreg[d + 0], Ks[j][d + 0], s0);
                s1 = fmaf(qreg[d + 1], Ks[j][d + 1], s1);
                s2 = fmaf(qreg[d + 2], Ks[j][d + 2], s2);
                s3 = fmaf(qreg[d + 3], Ks[j][d + 3], s3);
            }
            const float sv = ((s0 + s1) + (s2 + s3)) * scale;
            if (sv > mval) {
                const float f = expf(mval - sv);
#pragma unroll
                for (int d = 0; d < 64; d++) acc[d] *= f;
                lsum *= f;
                mval = sv;
            }
            const float p = expf(sv - mval);
            lsum += p;
#pragma unroll
            for (int d = 0; d < 64; d++)
                acc[d] = fmaf(p, Vs[j][d], acc[d]);
        }
        __syncthreads();
    }

    const float invl = 1.0f / lsum;
    float* orow = ctx + (size_t)(b * SEQ + qi) * D_MODEL + h * 64;
#pragma unroll
    for (int d = 0; d < 64; d += 4) {
        float4 o;
        o.x = acc[d + 0] * invl;
        o.y = acc[d + 1] * invl;
        o.z = acc[d + 2] * invl;
        o.w = acc[d + 3] * invl;
        *(float4*)(orow + d) = o;
    }
}

// ---------------------------------------------------------------------------
// Launch
// ---------------------------------------------------------------------------
extern "C" void kernel_launch(void* const* d_in, const int* in_sizes, int n_in,
                              void* d_out, int out_size)
{
    const float* x      = (const float*)d_in[0];
    const float* qkv_w  = (const float*)d_in[1];
    const float* qkv_b  = (const float*)d_in[2];
    const float* proj_w = (const float*)d_in[3];
    const float* proj_b = (const float*)d_in[4];
    float* out = (float*)d_out;

    float *p_qkv, *p_q, *p_k, *p_v, *p_ctx;
    cudaGetSymbolAddress((void**)&p_qkv, g_qkv);
    cudaGetSymbolAddress((void**)&p_q,   g_q);
    cudaGetSymbolAddress((void**)&p_k,   g_k);
    cudaGetSymbolAddress((void**)&p_v,   g_v);
    cudaGetSymbolAddress((void**)&p_ctx, g_ctx);

    cudaFuncSetAttribute(gemm_tf32_kernel,
                         cudaFuncAttributeMaxDynamicSharedMemorySize,
                         GEMM_SMEM_BYTES);

    // 1) QKV projection: [4096,1024] x [3072,1024]^T -> [4096,3072]
    gemm_tf32_kernel<<<dim3(QKV_N / GBN, M_TOT / GBM), 256, GEMM_SMEM_BYTES>>>(
        x, qkv_w, qkv_b, p_qkv, M_TOT, QKV_N, D_MODEL);

    // 2) RoPE + split into [B,H,S,Dh]
    {
        const int total = BATCH * SEQ * N_HEADS * D_HEAD;
        rope_split_kernel<<<(total + 255) / 256, 256>>>(p_qkv, p_q, p_k, p_v);
    }

    // 3) Causal flash attention -> ctx [B,S,D]
    flash_attn_kernel<<<dim3(SEQ / 128, N_HEADS, BATCH), 128>>>(p_q, p_k, p_v, p_ctx);

    // 4) Output projection: [4096,1024] x [1024,1024]^T -> [4096,1024]
    gemm_tf32_kernel<<<dim3(D_MODEL / GBN, M_TOT / GBM), 256, GEMM_SMEM_BYTES>>>(
        p_ctx, proj_w, proj_b, out, M_TOT, D_MODEL, D_MODEL);
}

// round 4
// speedup vs baseline: 3.3015x; 2.2306x over previous
#include <cuda_runtime.h>
#include <math.h>
#include <stdint.h>

// Problem constants
#define D_MODEL 1024
#define N_HEADS 16
#define D_HEAD  64
#define BATCH   2
#define SEQ     2048
#define M_TOT   (BATCH * SEQ)       // 4096
#define QKV_N   (3 * D_MODEL)       // 3072

// ---------------------------------------------------------------------------
// Scratch (no allocs allowed -> __device__ globals)
// ---------------------------------------------------------------------------
__device__ float g_qkv[(size_t)M_TOT * QKV_N];                    // 48 MB
__device__ float g_q[(size_t)BATCH * N_HEADS * SEQ * D_HEAD];     // 16 MB
__device__ float g_k[(size_t)BATCH * N_HEADS * SEQ * D_HEAD];     // 16 MB
__device__ float g_v[(size_t)BATCH * N_HEADS * SEQ * D_HEAD];     // 16 MB
__device__ float g_ctx[(size_t)M_TOT * D_MODEL];                  // 16 MB

// ---------------------------------------------------------------------------
// Common PTX helpers
// ---------------------------------------------------------------------------
__device__ __forceinline__ uint32_t cvt_tf32(float f) {
    uint32_t u;
    asm volatile("cvt.rna.tf32.f32 %0, %1;" : "=r"(u) : "f"(f));
    return u;
}

__device__ __forceinline__ void mma_tf32(float c[4], const uint32_t a[4],
                                         const uint32_t b[2]) {
    asm volatile(
        "mma.sync.aligned.m16n8k8.row.col.f32.tf32.tf32.f32 "
        "{%0,%1,%2,%3}, {%4,%5,%6,%7}, {%8,%9}, {%0,%1,%2,%3};"
        : "+f"(c[0]), "+f"(c[1]), "+f"(c[2]), "+f"(c[3])
        : "r"(a[0]), "r"(a[1]), "r"(a[2]), "r"(a[3]), "r"(b[0]), "r"(b[1]));
}

#define CP_ASYNC16(dst, src) \
    asm volatile("cp.async.cg.shared.global [%0], [%1], 16;" :: "r"(dst), "l"(src))
#define CP_COMMIT() asm volatile("cp.async.commit_group;")
#define CP_WAIT0()  asm volatile("cp.async.wait_group 0;" ::: "memory")

__device__ __forceinline__ uint32_t smem_u32(const void* p) {
    uint32_t a;
    asm("{ .reg .u64 t; cvta.to.shared.u64 t, %1; cvt.u32.u64 %0, t; }"
        : "=r"(a) : "l"(p));
    return a;
}

// ---------------------------------------------------------------------------
// tf32 tensor-core GEMM: C[m][n] = sum_k A[m][k]*W[n][k] + bias[n]
// ---------------------------------------------------------------------------
#define GBM 128
#define GBN 128
#define GBK 32
#define GPAD 36
#define ABUF (GBM * GPAD)
#define BBUF (GBN * GPAD)
#define GEMM_SMEM_BYTES ((2 * ABUF + 2 * BBUF) * 4)   // 73728

__global__ __launch_bounds__(256) void gemm_tf32_kernel(
    const float* __restrict__ A, const float* __restrict__ W,
    const float* __restrict__ bias, float* __restrict__ C,
    int M, int N, int K)
{
    extern __shared__ float smem[];
    float* As = smem;
    float* Bs = smem + 2 * ABUF;

    const int tid  = threadIdx.x;
    const int warp = tid >> 5;
    const int lane = tid & 31;
    const int warpM = warp >> 2;
    const int warpN = warp & 3;
    const int g   = lane >> 2;
    const int tig = lane & 3;

    const int m0 = blockIdx.y * GBM;
    const int n0 = blockIdx.x * GBN;

    float acc[4][4][4];
#pragma unroll
    for (int i = 0; i < 4; i++)
#pragma unroll
        for (int j = 0; j < 4; j++)
#pragma unroll
            for (int r = 0; r < 4; r++) acc[i][j][r] = 0.0f;

    const uint32_t sA = smem_u32(As);
    const uint32_t sB = smem_u32(Bs);

    const int nkb = K / GBK;

    auto issue_stage = [&](int kb, int buf) {
#pragma unroll
        for (int i = 0; i < 4; i++) {
            const int idx = tid + i * 256;
            const int row = idx >> 3;
            const int c4  = idx & 7;
            const float* gsrcA = A + (size_t)(m0 + row) * K + kb * GBK + c4 * 4;
            const float* gsrcB = W + (size_t)(n0 + row) * K + kb * GBK + c4 * 4;
            const uint32_t off = (uint32_t)((row * GPAD + c4 * 4) * 4);
            CP_ASYNC16(sA + (uint32_t)(buf * ABUF * 4) + off, gsrcA);
            CP_ASYNC16(sB + (uint32_t)(buf * BBUF * 4) + off, gsrcB);
        }
    };

    issue_stage(0, 0);
    CP_COMMIT();

    for (int kb = 0; kb < nkb; kb++) {
        CP_WAIT0();
        __syncthreads();
        if (kb + 1 < nkb) {
            issue_stage(kb + 1, (kb + 1) & 1);
            CP_COMMIT();
        }

        const float* Ab = As + (kb & 1) * ABUF;
        const float* Bb = Bs + (kb & 1) * BBUF;

#pragma unroll
        for (int ks = 0; ks < 4; ks++) {
            const int k8 = ks * 8;
            uint32_t aF[4][4];
#pragma unroll
            for (int mt = 0; mt < 4; mt++) {
                const int mr = warpM * 64 + mt * 16;
                aF[mt][0] = cvt_tf32(Ab[(mr + g)     * GPAD + k8 + tig]);
                aF[mt][1] = cvt_tf32(Ab[(mr + g + 8) * GPAD + k8 + tig]);
                aF[mt][2] = cvt_tf32(Ab[(mr + g)     * GPAD + k8 + tig + 4]);
                aF[mt][3] = cvt_tf32(Ab[(mr + g + 8) * GPAD + k8 + tig + 4]);
            }
            uint32_t bF[4][2];
#pragma unroll
            for (int nt = 0; nt < 4; nt++) {
                const int nr = warpN * 32 + nt * 8 + g;
                bF[nt][0] = cvt_tf32(Bb[nr * GPAD + k8 + tig]);
                bF[nt][1] = cvt_tf32(Bb[nr * GPAD + k8 + tig + 4]);
            }
#pragma unroll
            for (int mt = 0; mt < 4; mt++)
#pragma unroll
                for (int nt = 0; nt < 4; nt++)
                    mma_tf32(acc[mt][nt], aF[mt], bF[nt]);
        }
        __syncthreads();
    }

#pragma unroll
    for (int mt = 0; mt < 4; mt++) {
        const int r0 = m0 + warpM * 64 + mt * 16 + g;
#pragma unroll
        for (int nt = 0; nt < 4; nt++) {
            const int col = n0 + warpN * 32 + nt * 8 + 2 * tig;
            const float2 b2 = *(const float2*)&bias[col];
            float2 o0, o1;
            o0.x = acc[mt][nt][0] + b2.x;
            o0.y = acc[mt][nt][1] + b2.y;
            o1.x = acc[mt][nt][2] + b2.x;
            o1.y = acc[mt][nt][3] + b2.y;
            *(float2*)&C[(size_t)r0 * N + col]       = o0;
            *(float2*)&C[(size_t)(r0 + 8) * N + col] = o1;
        }
    }
}

// ---------------------------------------------------------------------------
// RoPE + split
// ---------------------------------------------------------------------------
__global__ void rope_split_kernel(const float* __restrict__ qkv,
                                  float* __restrict__ Q,
                                  float* __restrict__ Kp,
                                  float* __restrict__ Vp)
{
    const int idx = blockIdx.x * blockDim.x + threadIdx.x;
    const int total = BATCH * SEQ * N_HEADS * D_HEAD;
    if (idx >= total) return;

    const int d = idx & 63;
    const int h = (idx >> 6) & (N_HEADS - 1);
    const int s = (idx >> 10) & (SEQ - 1);
    const int b = idx >> 21;

    const float* row = qkv + (size_t)(b * SEQ + s) * QKV_N;
    const int hd = h * 64 + d;
    const int hp = h * 64 + (d ^ 32);

    const float qv = row[hd];
    const float kv = row[D_MODEL + hd];
    const float vv = row[2 * D_MODEL + hd];
    const float qp = row[hp];
    const float kp = row[D_MODEL + hp];

    const int j = d & 31;
    const float inv = powf(10000.0f, -(float)j / 32.0f);
    const float ang = (float)s * inv;
    const float c = cosf(ang);
    const float sn = sinf(ang);

    const float qr = (d < 32) ? -qp : qp;
    const float kr = (d < 32) ? -kp : kp;

    const size_t o = ((size_t)(b * N_HEADS + h) * SEQ + s) * D_HEAD + d;
    Q[o] = qv * c + qr * sn;
    Kp[o] = kv * c + kr * sn;
    Vp[o] = vv;
}

// ---------------------------------------------------------------------------
// Tensor-core causal flash attention (tf32 mma, fp32 softmax).
// 128 queries/CTA, 8 warps x 16 rows. KV tiles of 64 keys, double-buffered
// cp.async. Q resident as tf32 A-fragments (scale folded in). Online softmax
// in registers. P converted to A-fragments via quad shuffles.
// K tile pitch 68 (bank g*4+tig -> conflict-free), V pitch 72 (tig*8+g).
// ---------------------------------------------------------------------------
#define FPK 68
#define FPV 72
#define FA_STAGE_K (64 * FPK)
#define FA_STAGE_V (64 * FPV)
#define FA_SMEM_BYTES ((2 * (FA_STAGE_K + FA_STAGE_V)) * 4)   // 71680

__global__ __launch_bounds__(256) void flash_attn_tc_kernel(
    const float* __restrict__ Q, const float* __restrict__ K,
    const float* __restrict__ V, float* __restrict__ ctx)
{
    extern __shared__ float fsm[];
    float* Ksm = fsm;                       // [2][64][FPK]
    float* Vsm = fsm + 2 * FA_STAGE_K;      // [2][64][FPV]
    const uint32_t sK = smem_u32(Ksm);
    const uint32_t sV = smem_u32(Vsm);

    const int qt = gridDim.x - 1 - blockIdx.x;   // heavy tiles first
    const int h  = blockIdx.y;
    const int b  = blockIdx.z;
    const int tid  = threadIdx.x;
    const int warp = tid >> 5;
    const int lane = tid & 31;
    const int g    = lane >> 2;
    const int tig  = lane & 3;

    const size_t headBase = (size_t)(b * N_HEADS + h) * SEQ * D_HEAD;
    const float* Qb = Q + headBase;
    const float* Kb = K + headBase;
    const float* Vb = V + headBase;

    const int q0w = qt * 128 + warp * 16;   // this warp's first query row

    // Resident Q fragments, pre-scaled by 1/sqrt(Dh)=0.125 (exact)
    uint32_t aQ[8][4];
#pragma unroll
    for (int kc = 0; kc < 8; kc++) {
        const int k8 = kc * 8;
        aQ[kc][0] = cvt_tf32(0.125f * Qb[(size_t)(q0w + g)     * 64 + k8 + tig]);
        aQ[kc][1] = cvt_tf32(0.125f * Qb[(size_t)(q0w + g + 8) * 64 + k8 + tig]);
        aQ[kc][2] = cvt_tf32(0.125f * Qb[(size_t)(q0w + g)     * 64 + k8 + tig + 4]);
        aQ[kc][3] = cvt_tf32(0.125f * Qb[(size_t)(q0w + g + 8) * 64 + k8 + tig + 4]);
    }

    float O[8][4];
#pragma unroll
    for (int nt = 0; nt < 8; nt++)
#pragma unroll
        for (int r = 0; r < 4; r++) O[nt][r] = 0.0f;
    float mrow[2] = {-1e30f, -1e30f};
    float lrow[2] = {0.0f, 0.0f};

    const int ntiles = (qt + 1) * 2;        // 64-key tiles

    auto load_stage = [&](int t, int buf) {
        const int t0 = t * 64;
#pragma unroll
        for (int i = 0; i < 4; i++) {
            const int idx = tid + i * 256;
            const int row = idx >> 4;        // 0..63
            const int c4  = (idx & 15) * 4;  // 0..60
            CP_ASYNC16(sK + (uint32_t)((buf * FA_STAGE_K + row * FPK + c4) * 4),
                       Kb + (size_t)(t0 + row) * 64 + c4);
            CP_ASYNC16(sV + (uint32_t)((buf * FA_STAGE_V + row * FPV + c4) * 4),
                       Vb + (size_t)(t0 + row) * 64 + c4);
        }
    };

    load_stage(0, 0);
    CP_COMMIT();

    for (int t = 0; t < ntiles; t++) {
        CP_WAIT0();
        __syncthreads();
        if (t + 1 < ntiles) {
            load_stage(t + 1, (t + 1) & 1);
            CP_COMMIT();
        }
        const float* Kt = Ksm + (t & 1) * FA_STAGE_K;
        const float* Vt = Vsm + (t & 1) * FA_STAGE_V;
        const int t0 = t * 64;

        // ---- S = Q K^T (rows g,g+8 ; cols 8nt+2tig,+1) ----
        float S[8][4];
#pragma unroll
        for (int nt = 0; nt < 8; nt++)
#pragma unroll
            for (int r = 0; r < 4; r++) S[nt][r] = 0.0f;

#pragma unroll
        for (int kc = 0; kc < 8; kc++) {
            const int k8 = kc * 8;
#pragma unroll
            for (int nt = 0; nt < 8; nt++) {
                uint32_t bK[2];
                const int krow = (nt * 8 + g) * FPK + k8 + tig;
                bK[0] = cvt_tf32(Kt[krow]);
                bK[1] = cvt_tf32(Kt[krow + 4]);
                mma_tf32(S[nt], aQ[kc], bK);
            }
        }

        // ---- causal mask ----
        if (t0 + 63 > q0w) {
            const int r0 = q0w + g;
            const int r1 = r0 + 8;
#pragma unroll
            for (int nt = 0; nt < 8; nt++) {
                const int c0 = t0 + nt * 8 + 2 * tig;
                if (c0     > r0) S[nt][0] = -1e30f;
                if (c0 + 1 > r0) S[nt][1] = -1e30f;
                if (c0     > r1) S[nt][2] = -1e30f;
                if (c0 + 1 > r1) S[nt][3] = -1e30f;
            }
        }

        // ---- online softmax ----
        float tm0 = -1e30f, tm1 = -1e30f;
#pragma unroll
        for (int nt = 0; nt < 8; nt++) {
            tm0 = fmaxf(tm0, fmaxf(S[nt][0], S[nt][1]));
            tm1 = fmaxf(tm1, fmaxf(S[nt][2], S[nt][3]));
        }
        tm0 = fmaxf(tm0, __shfl_xor_sync(0xffffffffu, tm0, 1));
        tm0 = fmaxf(tm0, __shfl_xor_sync(0xffffffffu, tm0, 2));
        tm1 = fmaxf(tm1, __shfl_xor_sync(0xffffffffu, tm1, 1));
        tm1 = fmaxf(tm1, __shfl_xor_sync(0xffffffffu, tm1, 2));

        const float mn0 = fmaxf(mrow[0], tm0);
        const float mn1 = fmaxf(mrow[1], tm1);
        const float al0 = __expf(mrow[0] - mn0);
        const float al1 = __expf(mrow[1] - mn1);
        mrow[0] = mn0; mrow[1] = mn1;

        float ps0 = 0.0f, ps1 = 0.0f;
#pragma unroll
        for (int nt = 0; nt < 8; nt++) {
            S[nt][0] = __expf(S[nt][0] - mn0); ps0 += S[nt][0];
            S[nt][1] = __expf(S[nt][1] - mn0); ps0 += S[nt][1];
            S[nt][2] = __expf(S[nt][2] - mn1); ps1 += S[nt][2];
            S[nt][3] = __expf(S[nt][3] - mn1); ps1 += S[nt][3];
        }
        ps0 += __shfl_xor_sync(0xffffffffu, ps0, 1);
        ps0 += __shfl_xor_sync(0xffffffffu, ps0, 2);
        ps1 += __shfl_xor_sync(0xffffffffu, ps1, 1);
        ps1 += __shfl_xor_sync(0xffffffffu, ps1, 2);
        lrow[0] = lrow[0] * al0 + ps0;
        lrow[1] = lrow[1] * al1 + ps1;

#pragma unroll
        for (int nt = 0; nt < 8; nt++) {
            O[nt][0] *= al0; O[nt][1] *= al0;
            O[nt][2] *= al1; O[nt][3] *= al1;
        }

        // ---- O += P V ----
        const int srcLo = (lane & ~3) | (tig >> 1);
        const int srcHi = srcLo + 2;
#pragma unroll
        for (int kc = 0; kc < 8; kc++) {
            // convert P chunk (accumulator layout) -> A fragment layout
            const float v0 = S[kc][0], v1 = S[kc][1];
            const float v2 = S[kc][2], v3 = S[kc][3];
            const float s00 = __shfl_sync(0xffffffffu, v0, srcLo);
            const float s01 = __shfl_sync(0xffffffffu, v1, srcLo);
            const float s10 = __shfl_sync(0xffffffffu, v0, srcHi);
            const float s11 = __shfl_sync(0xffffffffu, v1, srcHi);
            const float s20 = __shfl_sync(0xffffffffu, v2, srcLo);
            const float s21 = __shfl_sync(0xffffffffu, v3, srcLo);
            const float s30 = __shfl_sync(0xffffffffu, v2, srcHi);
            const float s31 = __shfl_sync(0xffffffffu, v3, srcHi);
            const bool odd = (tig & 1);
            uint32_t aP[4];
            aP[0] = cvt_tf32(odd ? s01 : s00);
            aP[1] = cvt_tf32(odd ? s21 : s20);
            aP[2] = cvt_tf32(odd ? s11 : s10);
            aP[3] = cvt_tf32(odd ? s31 : s30);

            const int kr0 = (kc * 8 + tig) * FPV + g;
            const int kr1 = (kc * 8 + tig + 4) * FPV + g;
#pragma unroll
            for (int nt = 0; nt < 8; nt++) {
                uint32_t bV[2];
                bV[0] = cvt_tf32(Vt[kr0 + nt * 8]);
                bV[1] = cvt_tf32(Vt[kr1 + nt * 8]);
                mma_tf32(O[nt], aP, bV);
            }
        }
        __syncthreads();
    }

    // ---- epilogue ----
    const float inv0 = 1.0f / lrow[0];
    const float inv1 = 1.0f / lrow[1];
    const int row0 = q0w + g;
    float* o0 = ctx + (size_t)(b * SEQ + row0) * D_MODEL + h * 64;
    float* o1 = ctx + (size_t)(b * SEQ + row0 + 8) * D_MODEL + h * 64;
#pragma unroll
    for (int nt = 0; nt < 8; nt++) {
        const int col = nt * 8 + 2 * tig;
        float2 w0, w1;
        w0.x = O[nt][0] * inv0; w0.y = O[nt][1] * inv0;
        w1.x = O[nt][2] * inv1; w1.y = O[nt][3] * inv1;
        *(float2*)(o0 + col) = w0;
        *(float2*)(o1 + col) = w1;
    }
}

// ---------------------------------------------------------------------------
// Launch
// ---------------------------------------------------------------------------
extern "C" void kernel_launch(void* const* d_in, const int* in_sizes, int n_in,
                              void* d_out, int out_size)
{
    const float* x      = (const float*)d_in[0];
    const float* qkv_w  = (const float*)d_in[1];
    const float* qkv_b  = (const float*)d_in[2];
    const float* proj_w = (const float*)d_in[3];
    const float* proj_b = (const float*)d_in[4];
    float* out = (float*)d_out;

    float *p_qkv, *p_q, *p_k, *p_v, *p_ctx;
    cudaGetSymbolAddress((void**)&p_qkv, g_qkv);
    cudaGetSymbolAddress((void**)&p_q,   g_q);
    cudaGetSymbolAddress((void**)&p_k,   g_k);
    cudaGetSymbolAddress((void**)&p_v,   g_v);
    cudaGetSymbolAddress((void**)&p_ctx, g_ctx);

    cudaFuncSetAttribute(gemm_tf32_kernel,
                         cudaFuncAttributeMaxDynamicSharedMemorySize,
                         GEMM_SMEM_BYTES);
    cudaFuncSetAttribute(flash_attn_tc_kernel,
                         cudaFuncAttributeMaxDynamicSharedMemorySize,
                         FA_SMEM_BYTES);

    // 1) QKV projection
    gemm_tf32_kernel<<<dim3(QKV_N / GBN, M_TOT / GBM), 256, GEMM_SMEM_BYTES>>>(
        x, qkv_w, qkv_b, p_qkv, M_TOT, QKV_N, D_MODEL);

    // 2) RoPE + split into [B,H,S,Dh]
    {
        const int total = BATCH * SEQ * N_HEADS * D_HEAD;
        rope_split_kernel<<<(total + 255) / 256, 256>>>(p_qkv, p_q, p_k, p_v);
    }

    // 3) Tensor-core causal flash attention -> ctx [B,S,D]
    flash_attn_tc_kernel<<<dim3(SEQ / 128, N_HEADS, BATCH), 256, FA_SMEM_BYTES>>>(
        p_q, p_k, p_v, p_ctx);

    // 4) Output projection
    gemm_tf32_kernel<<<dim3(D_MODEL / GBN, M_TOT / GBM), 256, GEMM_SMEM_BYTES>>>(
        p_ctx, proj_w, proj_b, out, M_TOT, D_MODEL, D_MODEL);
}

// round 5
// speedup vs baseline: 4.1770x; 1.2652x over previous
#include <cuda_runtime.h>
#include <math.h>
#include <stdint.h>

// Problem constants
#define D_MODEL 1024
#define N_HEADS 16
#define D_HEAD  64
#define BATCH   2
#define SEQ     2048
#define M_TOT   (BATCH * SEQ)       // 4096
#define QKV_N   (3 * D_MODEL)       // 3072

// ---------------------------------------------------------------------------
// Scratch (no allocs allowed -> __device__ globals)
// ---------------------------------------------------------------------------
__device__ float g_qkv[(size_t)M_TOT * QKV_N];                    // 48 MB
__device__ float g_q[(size_t)BATCH * N_HEADS * SEQ * D_HEAD];     // 16 MB
__device__ float g_k[(size_t)BATCH * N_HEADS * SEQ * D_HEAD];     // 16 MB
__device__ float g_v[(size_t)BATCH * N_HEADS * SEQ * D_HEAD];     // 16 MB
__device__ float g_ctx[(size_t)M_TOT * D_MODEL];                  // 16 MB
__device__ float g_xc[(size_t)M_TOT * D_MODEL];                   // 16 MB (x, tf32+perm)
__device__ float g_wq[(size_t)QKV_N * D_MODEL];                   // 12 MB
__device__ float g_wp[(size_t)D_MODEL * D_MODEL];                 // 4 MB

// ---------------------------------------------------------------------------
// Helpers
// ---------------------------------------------------------------------------
__device__ __forceinline__ float tf32r(float f) {
    uint32_t u;
    asm("cvt.rna.tf32.f32 %0, %1;" : "=r"(u) : "f"(f));
    return __uint_as_float(u);
}
__device__ __forceinline__ uint32_t cvt_tf32(float f) {
    uint32_t u;
    asm volatile("cvt.rna.tf32.f32 %0, %1;" : "=r"(u) : "f"(f));
    return u;
}
// permute k within 8-groups: [0,4,1,5,2,6,3,7] -> frag pairs become adjacent
__device__ __forceinline__ int perm8(int k) {
    return (k & ~7) | ((k & 3) << 1) | ((k & 4) >> 2);
}

__device__ __forceinline__ void mma_tf32(float c[4], const uint32_t a[4],
                                         const uint32_t b[2]) {
    asm volatile(
        "mma.sync.aligned.m16n8k8.row.col.f32.tf32.tf32.f32 "
        "{%0,%1,%2,%3}, {%4,%5,%6,%7}, {%8,%9}, {%0,%1,%2,%3};"
        : "+f"(c[0]), "+f"(c[1]), "+f"(c[2]), "+f"(c[3])
        : "r"(a[0]), "r"(a[1]), "r"(a[2]), "r"(a[3]), "r"(b[0]), "r"(b[1]));
}

#define CP_ASYNC16(dst, src) \
    asm volatile("cp.async.cg.shared.global [%0], [%1], 16;" :: "r"(dst), "l"(src))
#define CP_COMMIT() asm volatile("cp.async.commit_group;")
#define CP_WAIT0()  asm volatile("cp.async.wait_group 0;" ::: "memory")

__device__ __forceinline__ uint32_t smem_u32(const void* p) {
    uint32_t a;
    asm("{ .reg .u64 t; cvta.to.shared.u64 t, %1; cvt.u32.u64 %0, t; }"
        : "=r"(a) : "l"(p));
    return a;
}

// ---------------------------------------------------------------------------
// Pre-convert: dst[i] = tf32_round(src at inverse-permuted index).
// Flat index ok: every matrix has innermost dim % 8 == 0.
// ---------------------------------------------------------------------------
__global__ void conv_perm_kernel(const float* __restrict__ src,
                                 float* __restrict__ dst, int n)
{
    const int idx = blockIdx.x * blockDim.x + threadIdx.x;
    if (idx >= n) return;
    const int j = idx & 7;
    const int orig = (idx & ~7) | (j >> 1) | ((j & 1) << 2);
    dst[idx] = tf32r(src[orig]);
}

// ---------------------------------------------------------------------------
// tf32 tensor-core GEMM on pre-rounded, k-permuted A and W.
// C[m][n] = sum_k A[m][k]*W[n][k] + bias[n]
// ---------------------------------------------------------------------------
#define GBM 128
#define GBN 128
#define GBK 32
#define GPAD 40                       // stride ≡ 8 (mod 32): LDS.64 conflict-free
#define ABUF (GBM * GPAD)
#define BBUF (GBN * GPAD)
#define GEMM_SMEM_BYTES ((2 * ABUF + 2 * BBUF) * 4)   // 81920

__global__ __launch_bounds__(256, 2) void gemm_tf32_kernel(
    const float* __restrict__ A, const float* __restrict__ W,
    const float* __restrict__ bias, float* __restrict__ C,
    int M, int N, int K)
{
    extern __shared__ float smem[];
    float* As = smem;
    float* Bs = smem + 2 * ABUF;

    const int tid  = threadIdx.x;
    const int warp = tid >> 5;
    const int lane = tid & 31;
    const int warpM = warp >> 2;
    const int warpN = warp & 3;
    const int g   = lane >> 2;
    const int tig = lane & 3;

    const int m0 = blockIdx.y * GBM;
    const int n0 = blockIdx.x * GBN;

    float acc[4][4][4];
#pragma unroll
    for (int i = 0; i < 4; i++)
#pragma unroll
        for (int j = 0; j < 4; j++)
#pragma unroll
            for (int r = 0; r < 4; r++) acc[i][j][r] = 0.0f;

    const uint32_t sA = smem_u32(As);
    const uint32_t sB = smem_u32(Bs);

    const int nkb = K / GBK;

    auto issue_stage = [&](int kb, int buf) {
#pragma unroll
        for (int i = 0; i < 4; i++) {
            const int idx = tid + i * 256;
            const int row = idx >> 3;
            const int c4  = idx & 7;
            const float* gsrcA = A + (size_t)(m0 + row) * K + kb * GBK + c4 * 4;
            const float* gsrcB = W + (size_t)(n0 + row) * K + kb * GBK + c4 * 4;
            const uint32_t off = (uint32_t)((row * GPAD + c4 * 4) * 4);
            CP_ASYNC16(sA + (uint32_t)(buf * ABUF * 4) + off, gsrcA);
            CP_ASYNC16(sB + (uint32_t)(buf * BBUF * 4) + off, gsrcB);
        }
    };

    issue_stage(0, 0);
    CP_COMMIT();

    for (int kb = 0; kb < nkb; kb++) {
        CP_WAIT0();
        __syncthreads();
        if (kb + 1 < nkb) {
            issue_stage(kb + 1, (kb + 1) & 1);
            CP_COMMIT();
        }

        const float* Ab = As + (kb & 1) * ABUF;
        const float* Bb = Bs + (kb & 1) * BBUF;

#pragma unroll
        for (int ks = 0; ks < 4; ks++) {
            const int k8 = ks * 8;
            uint32_t aF[4][4];
#pragma unroll
            for (int mt = 0; mt < 4; mt++) {
                const int mr = warpM * 64 + mt * 16;
                const float2 lo = *(const float2*)&Ab[(mr + g)     * GPAD + k8 + 2 * tig];
                const float2 hi = *(const float2*)&Ab[(mr + g + 8) * GPAD + k8 + 2 * tig];
                aF[mt][0] = __float_as_uint(lo.x);
                aF[mt][2] = __float_as_uint(lo.y);
                aF[mt][1] = __float_as_uint(hi.x);
                aF[mt][3] = __float_as_uint(hi.y);
            }
            uint32_t bF[4][2];
#pragma unroll
            for (int nt = 0; nt < 4; nt++) {
                const int nr = warpN * 32 + nt * 8 + g;
                const float2 bv = *(const float2*)&Bb[nr * GPAD + k8 + 2 * tig];
                bF[nt][0] = __float_as_uint(bv.x);
                bF[nt][1] = __float_as_uint(bv.y);
            }
#pragma unroll
            for (int mt = 0; mt < 4; mt++)
#pragma unroll
                for (int nt = 0; nt < 4; nt++)
                    mma_tf32(acc[mt][nt], aF[mt], bF[nt]);
        }
        __syncthreads();
    }

#pragma unroll
    for (int mt = 0; mt < 4; mt++) {
        const int r0 = m0 + warpM * 64 + mt * 16 + g;
#pragma unroll
        for (int nt = 0; nt < 4; nt++) {
            const int col = n0 + warpN * 32 + nt * 8 + 2 * tig;
            const float2 b2 = *(const float2*)&bias[col];
            float2 o0, o1;
            o0.x = acc[mt][nt][0] + b2.x;
            o0.y = acc[mt][nt][1] + b2.y;
            o1.x = acc[mt][nt][2] + b2.x;
            o1.y = acc[mt][nt][3] + b2.y;
            *(float2*)&C[(size_t)r0 * N + col]       = o0;
            *(float2*)&C[(size_t)(r0 + 8) * N + col] = o1;
        }
    }
}

// ---------------------------------------------------------------------------
// RoPE + split. Q,K written tf32-rounded with d permuted (mma k-dim);
// V written tf32-rounded, d unpermuted (mma n-dim).
// ---------------------------------------------------------------------------
__global__ void rope_split_kernel(const float* __restrict__ qkv,
                                  float* __restrict__ Q,
                                  float* __restrict__ Kp,
                                  float* __restrict__ Vp)
{
    const int idx = blockIdx.x * blockDim.x + threadIdx.x;
    const int total = BATCH * SEQ * N_HEADS * D_HEAD;
    if (idx >= total) return;

    const int d = idx & 63;
    const int h = (idx >> 6) & (N_HEADS - 1);
    const int s = (idx >> 10) & (SEQ - 1);
    const int b = idx >> 21;

    const float* row = qkv + (size_t)(b * SEQ + s) * QKV_N;
    const int hd = h * 64 + d;
    const int hp = h * 64 + (d ^ 32);

    const float qv = row[hd];
    const float kv = row[D_MODEL + hd];
    const float vv = row[2 * D_MODEL + hd];
    const float qp = row[hp];
    const float kp = row[D_MODEL + hp];

    const int j = d & 31;
    const float inv = powf(10000.0f, -(float)j / 32.0f);
    const float ang = (float)s * inv;
    const float c = cosf(ang);
    const float sn = sinf(ang);

    const float qr = (d < 32) ? -qp : qp;
    const float kr = (d < 32) ? -kp : kp;

    const size_t o = ((size_t)(b * N_HEADS + h) * SEQ + s) * D_HEAD;
    const int dp = perm8(d);
    Q[o + dp] = tf32r(qv * c + qr * sn);
    Kp[o + dp] = tf32r(kv * c + kr * sn);
    Vp[o + d] = tf32r(vv);
}

// ---------------------------------------------------------------------------
// Tensor-core causal flash attention (tf32 mma, fp32 softmax).
// Inputs pre-rounded; Q/K d-permuted -> float2 fragment loads, no cvt.
// Epilogue writes ctx tf32-rounded + d-permuted (feeds proj GEMM).
// ---------------------------------------------------------------------------
#define FPK 72
#define FPV 72
#define FA_STAGE_K (64 * FPK)
#define FA_STAGE_V (64 * FPV)
#define FA_SMEM_BYTES ((2 * (FA_STAGE_K + FA_STAGE_V)) * 4)   // 73728

__global__ __launch_bounds__(256) void flash_attn_tc_kernel(
    const float* __restrict__ Q, const float* __restrict__ K,
    const float* __restrict__ V, float* __restrict__ ctx)
{
    extern __shared__ float fsm[];
    float* Ksm = fsm;                       // [2][64][FPK]
    float* Vsm = fsm + 2 * FA_STAGE_K;      // [2][64][FPV]
    const uint32_t sK = smem_u32(Ksm);
    const uint32_t sV = smem_u32(Vsm);

    const int qt = gridDim.x - 1 - blockIdx.x;   // heavy tiles first
    const int h  = blockIdx.y;
    const int b  = blockIdx.z;
    const int tid  = threadIdx.x;
    const int warp = tid >> 5;
    const int lane = tid & 31;
    const int g    = lane >> 2;
    const int tig  = lane & 3;

    const size_t headBase = (size_t)(b * N_HEADS + h) * SEQ * D_HEAD;
    const float* Qb = Q + headBase;
    const float* Kb = K + headBase;
    const float* Vb = V + headBase;

    const int q0w = qt * 128 + warp * 16;

    // Resident Q fragments (pre-rounded, permuted); 0.125 scale is exact.
    uint32_t aQ[8][4];
#pragma unroll
    for (int kc = 0; kc < 8; kc++) {
        const float2 lo = *(const float2*)&Qb[(size_t)(q0w + g)     * 64 + kc * 8 + 2 * tig];
        const float2 hi = *(const float2*)&Qb[(size_t)(q0w + g + 8) * 64 + kc * 8 + 2 * tig];
        aQ[kc][0] = __float_as_uint(0.125f * lo.x);
        aQ[kc][2] = __float_as_uint(0.125f * lo.y);
        aQ[kc][1] = __float_as_uint(0.125f * hi.x);
        aQ[kc][3] = __float_as_uint(0.125f * hi.y);
    }

    float O[8][4];
#pragma unroll
    for (int nt = 0; nt < 8; nt++)
#pragma unroll
        for (int r = 0; r < 4; r++) O[nt][r] = 0.0f;
    float mrow[2] = {-1e30f, -1e30f};
    float lrow[2] = {0.0f, 0.0f};

    const int ntiles = (qt + 1) * 2;

    auto load_stage = [&](int t, int buf) {
        const int t0 = t * 64;
#pragma unroll
        for (int i = 0; i < 4; i++) {
            const int idx = tid + i * 256;
            const int row = idx >> 4;
            const int c4  = (idx & 15) * 4;
            CP_ASYNC16(sK + (uint32_t)((buf * FA_STAGE_K + row * FPK + c4) * 4),
                       Kb + (size_t)(t0 + row) * 64 + c4);
            CP_ASYNC16(sV + (uint32_t)((buf * FA_STAGE_V + row * FPV + c4) * 4),
                       Vb + (size_t)(t0 + row) * 64 + c4);
        }
    };

    load_stage(0, 0);
    CP_COMMIT();

    for (int t = 0; t < ntiles; t++) {
        CP_WAIT0();
        __syncthreads();
        if (t + 1 < ntiles) {
            load_stage(t + 1, (t + 1) & 1);
            CP_COMMIT();
        }
        const float* Kt = Ksm + (t & 1) * FA_STAGE_K;
        const float* Vt = Vsm + (t & 1) * FA_STAGE_V;
        const int t0 = t * 64;

        // ---- S = Q K^T ----
        float S[8][4];
#pragma unroll
        for (int nt = 0; nt < 8; nt++)
#pragma unroll
            for (int r = 0; r < 4; r++) S[nt][r] = 0.0f;

#pragma unroll
        for (int kc = 0; kc < 8; kc++) {
            const int k8 = kc * 8;
#pragma unroll
            for (int nt = 0; nt < 8; nt++) {
                const float2 kv2 = *(const float2*)&Kt[(nt * 8 + g) * FPK + k8 + 2 * tig];
                uint32_t bK[2];
                bK[0] = __float_as_uint(kv2.x);
                bK[1] = __float_as_uint(kv2.y);
                mma_tf32(S[nt], aQ[kc], bK);
            }
        }

        // ---- causal mask ----
        if (t0 + 63 > q0w) {
            const int r0 = q0w + g;
            const int r1 = r0 + 8;
#pragma unroll
            for (int nt = 0; nt < 8; nt++) {
                const int c0 = t0 + nt * 8 + 2 * tig;
                if (c0     > r0) S[nt][0] = -1e30f;
                if (c0 + 1 > r0) S[nt][1] = -1e30f;
                if (c0     > r1) S[nt][2] = -1e30f;
                if (c0 + 1 > r1) S[nt][3] = -1e30f;
            }
        }

        // ---- online softmax ----
        float tm0 = -1e30f, tm1 = -1e30f;
#pragma unroll
        for (int nt = 0; nt < 8; nt++) {
            tm0 = fmaxf(tm0, fmaxf(S[nt][0], S[nt][1]));
            tm1 = fmaxf(tm1, fmaxf(S[nt][2], S[nt][3]));
        }
        tm0 = fmaxf(tm0, __shfl_xor_sync(0xffffffffu, tm0, 1));
        tm0 = fmaxf(tm0, __shfl_xor_sync(0xffffffffu, tm0, 2));
        tm1 = fmaxf(tm1, __shfl_xor_sync(0xffffffffu, tm1, 1));
        tm1 = fmaxf(tm1, __shfl_xor_sync(0xffffffffu, tm1, 2));

        const float mn0 = fmaxf(mrow[0], tm0);
        const float mn1 = fmaxf(mrow[1], tm1);
        const float al0 = __expf(mrow[0] - mn0);
        const float al1 = __expf(mrow[1] - mn1);
        mrow[0] = mn0; mrow[1] = mn1;

        float ps0 = 0.0f, ps1 = 0.0f;
#pragma unroll
        for (int nt = 0; nt < 8; nt++) {
            S[nt][0] = __expf(S[nt][0] - mn0); ps0 += S[nt][0];
            S[nt][1] = __expf(S[nt][1] - mn0); ps0 += S[nt][1];
            S[nt][2] = __expf(S[nt][2] - mn1); ps1 += S[nt][2];
            S[nt][3] = __expf(S[nt][3] - mn1); ps1 += S[nt][3];
        }
        ps0 += __shfl_xor_sync(0xffffffffu, ps0, 1);
        ps0 += __shfl_xor_sync(0xffffffffu, ps0, 2);
        ps1 += __shfl_xor_sync(0xffffffffu, ps1, 1);
        ps1 += __shfl_xor_sync(0xffffffffu, ps1, 2);
        lrow[0] = lrow[0] * al0 + ps0;
        lrow[1] = lrow[1] * al1 + ps1;

#pragma unroll
        for (int nt = 0; nt < 8; nt++) {
            O[nt][0] *= al0; O[nt][1] *= al0;
            O[nt][2] *= al1; O[nt][3] *= al1;
        }

        // ---- O += P V ----
        const int srcLo = (lane & ~3) | (tig >> 1);
        const int srcHi = srcLo + 2;
#pragma unroll
        for (int kc = 0; kc < 8; kc++) {
            const float v0 = S[kc][0], v1 = S[kc][1];
            const float v2 = S[kc][2], v3 = S[kc][3];
            const float s00 = __shfl_sync(0xffffffffu, v0, srcLo);
            const float s01 = __shfl_sync(0xffffffffu, v1, srcLo);
            const float s10 = __shfl_sync(0xffffffffu, v0, srcHi);
            const float s11 = __shfl_sync(0xffffffffu, v1, srcHi);
            const float s20 = __shfl_sync(0xffffffffu, v2, srcLo);
            const float s21 = __shfl_sync(0xffffffffu, v3, srcLo);
            const float s30 = __shfl_sync(0xffffffffu, v2, srcHi);
            const float s31 = __shfl_sync(0xffffffffu, v3, srcHi);
            const bool odd = (tig & 1);
            uint32_t aP[4];
            aP[0] = cvt_tf32(odd ? s01 : s00);
            aP[1] = cvt_tf32(odd ? s21 : s20);
            aP[2] = cvt_tf32(odd ? s11 : s10);
            aP[3] = cvt_tf32(odd ? s31 : s30);

            const int kr0 = (kc * 8 + tig) * FPV + g;
            const int kr1 = (kc * 8 + tig + 4) * FPV + g;
#pragma unroll
            for (int nt = 0; nt < 8; nt++) {
                uint32_t bV[2];
                bV[0] = __float_as_uint(Vt[kr0 + nt * 8]);
                bV[1] = __float_as_uint(Vt[kr1 + nt * 8]);
                mma_tf32(O[nt], aP, bV);
            }
        }
        __syncthreads();
    }

    // ---- epilogue: tf32-round + d-perm for the proj GEMM's A operand ----
    const float inv0 = 1.0f / lrow[0];
    const float inv1 = 1.0f / lrow[1];
    const int row0 = q0w + g;
    float* o0 = ctx + (size_t)(b * SEQ + row0) * D_MODEL + h * 64;
    float* o1 = ctx + (size_t)(b * SEQ + row0 + 8) * D_MODEL + h * 64;
#pragma unroll
    for (int nt = 0; nt < 8; nt++) {
        const int c0 = nt * 8 + 2 * tig;
        const int p0 = perm8(c0);
        const int p1 = perm8(c0 + 1);
        o0[p0] = tf32r(O[nt][0] * inv0);
        o0[p1] = tf32r(O[nt][1] * inv0);
        o1[p0] = tf32r(O[nt][2] * inv1);
        o1[p1] = tf32r(O[nt][3] * inv1);
    }
}

// ---------------------------------------------------------------------------
// Launch
// ---------------------------------------------------------------------------
extern "C" void kernel_launch(void* const* d_in, const int* in_sizes, int n_in,
                              void* d_out, int out_size)
{
    const float* x      = (const float*)d_in[0];
    const float* qkv_w  = (const float*)d_in[1];
    const float* qkv_b  = (const float*)d_in[2];
    const float* proj_w = (const float*)d_in[3];
    const float* proj_b = (const float*)d_in[4];
    float* out = (float*)d_out;

    float *p_qkv, *p_q, *p_k, *p_v, *p_ctx, *p_xc, *p_wq, *p_wp;
    cudaGetSymbolAddress((void**)&p_qkv, g_qkv);
    cudaGetSymbolAddress((void**)&p_q,   g_q);
    cudaGetSymbolAddress((void**)&p_k,   g_k);
    cudaGetSymbolAddress((void**)&p_v,   g_v);
    cudaGetSymbolAddress((void**)&p_ctx, g_ctx);
    cudaGetSymbolAddress((void**)&p_xc,  g_xc);
    cudaGetSymbolAddress((void**)&p_wq,  g_wq);
    cudaGetSymbolAddress((void**)&p_wp,  g_wp);

    cudaFuncSetAttribute(gemm_tf32_kernel,
                         cudaFuncAttributeMaxDynamicSharedMemorySize,
                         GEMM_SMEM_BYTES);
    cudaFuncSetAttribute(flash_attn_tc_kernel,
                         cudaFuncAttributeMaxDynamicSharedMemorySize,
                         FA_SMEM_BYTES);

    // 0) Pre-round to tf32 + k-permute
    {
        const int nx = M_TOT * D_MODEL;
        const int nwq = QKV_N * D_MODEL;
        const int nwp = D_MODEL * D_MODEL;
        conv_perm_kernel<<<(nx + 255) / 256, 256>>>(x, p_xc, nx);
        conv_perm_kernel<<<(nwq + 255) / 256, 256>>>(qkv_w, p_wq, nwq);
        conv_perm_kernel<<<(nwp + 255) / 256, 256>>>(proj_w, p_wp, nwp);
    }

    // 1) QKV projection
    gemm_tf32_kernel<<<dim3(QKV_N / GBN, M_TOT / GBM), 256, GEMM_SMEM_BYTES>>>(
        p_xc, p_wq, qkv_b, p_qkv, M_TOT, QKV_N, D_MODEL);

    // 2) RoPE + split into [B,H,S,Dh] (tf32-rounded, Q/K d-permuted)
    {
        const int total = BATCH * SEQ * N_HEADS * D_HEAD;
        rope_split_kernel<<<(total + 255) / 256, 256>>>(p_qkv, p_q, p_k, p_v);
    }

    // 3) Tensor-core causal flash attention -> ctx (rounded+permuted)
    flash_attn_tc_kernel<<<dim3(SEQ / 128, N_HEADS, BATCH), 256, FA_SMEM_BYTES>>>(
        p_q, p_k, p_v, p_ctx);

    // 4) Output projection
    gemm_tf32_kernel<<<dim3(D_MODEL / GBN, M_TOT / GBM), 256, GEMM_SMEM_BYTES>>>(
        p_ctx, p_wp, proj_b, out, M_TOT, D_MODEL, D_MODEL);
}